// round 1
// baseline (speedup 1.0000x reference)
#include <cuda_runtime.h>
#include <cuda_bf16.h>

#define NTOK 8192
#define DIN  256
#define DOUT 256
#define NE   16
#define NH   512

// Scratch (device globals; no runtime allocation allowed)
__device__ float g_Hg[NTOK * NH];      // gating hidden activations
__device__ int   g_cnt[NE];            // per-expert token counts
__device__ int   g_rtok[NE * NTOK];    // per-expert token lists
__device__ float g_rgate[NE * NTOK];   // per-expert gate values

// ---------------------------------------------------------------------------
// 32-row x 512-col register-blocked GEMM tile.
// S: smem [32][kdim] (row-major, 16B aligned). W: global, row i at W + i*ws.
// 256 threads, each owns cols (tid, tid+256), 32-row accumulators.
// ---------------------------------------------------------------------------
__device__ __forceinline__ void gemm32_512(
    const float* __restrict__ S, int kdim,
    const float* __restrict__ W, long ws,
    const float* __restrict__ bias,
    float* O, long ostride, bool do_relu, int tid)
{
    const int c0 = tid, c1 = tid + 256;
    float acc0[32], acc1[32];
#pragma unroll
    for (int r = 0; r < 32; ++r) { acc0[r] = 0.f; acc1[r] = 0.f; }

    for (int i = 0; i < kdim; i += 4) {
        const float* wp = W + (long)i * ws;
        float a0 = wp[c0]; float b0 = wp[c1]; wp += ws;
        float a1 = wp[c0]; float b1 = wp[c1]; wp += ws;
        float a2 = wp[c0]; float b2 = wp[c1]; wp += ws;
        float a3 = wp[c0]; float b3 = wp[c1];
#pragma unroll
        for (int r = 0; r < 32; ++r) {
            float4 xv = *(const float4*)(S + r * kdim + i);  // broadcast LDS.128
            acc0[r] = fmaf(xv.x, a0, acc0[r]);
            acc1[r] = fmaf(xv.x, b0, acc1[r]);
            acc0[r] = fmaf(xv.y, a1, acc0[r]);
            acc1[r] = fmaf(xv.y, b1, acc1[r]);
            acc0[r] = fmaf(xv.z, a2, acc0[r]);
            acc1[r] = fmaf(xv.z, b2, acc1[r]);
            acc0[r] = fmaf(xv.w, a3, acc0[r]);
            acc1[r] = fmaf(xv.w, b3, acc1[r]);
        }
    }
    float bb0 = bias[c0], bb1 = bias[c1];
#pragma unroll
    for (int r = 0; r < 32; ++r) {
        float v0 = acc0[r] + bb0, v1 = acc1[r] + bb1;
        if (do_relu) { v0 = fmaxf(v0, 0.f); v1 = fmaxf(v1, 0.f); }
        O[(long)r * ostride + c0] = v0;
        O[(long)r * ostride + c1] = v1;
    }
}

// ---------------------------------------------------------------------------
// K0: zero routing counters
// ---------------------------------------------------------------------------
__global__ void zero_cnt_kernel() {
    if (threadIdx.x < NE) g_cnt[threadIdx.x] = 0;
}

// ---------------------------------------------------------------------------
// K1: gating hidden = relu(x @ gate_w + gate_b)  -> g_Hg [8192, 512]
// ---------------------------------------------------------------------------
__global__ __launch_bounds__(256) void gate_h_kernel(
    const float* __restrict__ x,
    const float* __restrict__ gw,
    const float* __restrict__ gb)
{
    __shared__ float Xs[32 * DIN];
    const int tid = threadIdx.x;
    const int t0 = blockIdx.x * 32;
    for (int idx = tid; idx < 32 * DIN; idx += 256)
        Xs[idx] = x[(long)t0 * DIN + idx];
    __syncthreads();
    gemm32_512(Xs, DIN, gw, NH, gb, g_Hg + (long)t0 * NH, NH, true, tid);
}

// ---------------------------------------------------------------------------
// K2: logits = Hg @ gate_out_w + gate_out_b; top-2; softmax; routing append
// 128 threads, 128 tokens per block.
// ---------------------------------------------------------------------------
__global__ __launch_bounds__(128) void gate_route_kernel(
    const float* __restrict__ gow,
    const float* __restrict__ gob)
{
    extern __shared__ float sm2[];
    float* Gw = sm2;               // [512*16]
    float* Gb = Gw + NH * NE;      // [16]
    float* Ht = Gb + 16;           // [128][65] padded

    const int tid = threadIdx.x;
    for (int idx = tid; idx < NH * NE; idx += 128) Gw[idx] = gow[idx];
    if (tid < NE) Gb[tid] = gob[tid];

    const int tok0 = blockIdx.x * 128;
    float acc[NE];
#pragma unroll
    for (int e = 0; e < NE; ++e) acc[e] = 0.f;

    for (int hb = 0; hb < NH; hb += 64) {
        __syncthreads();
        for (int idx = tid; idx < 128 * 64; idx += 128) {
            int r = idx >> 6, h = idx & 63;
            Ht[r * 65 + h] = g_Hg[(long)(tok0 + r) * NH + hb + h];
        }
        __syncthreads();
#pragma unroll 8
        for (int hl = 0; hl < 64; ++hl) {
            float v = Ht[tid * 65 + hl];
            const float4* gp = (const float4*)(Gw + (hb + hl) * NE);
            float4 g0v = gp[0], g1v = gp[1], g2v = gp[2], g3v = gp[3];
            acc[0]  = fmaf(v, g0v.x, acc[0]);
            acc[1]  = fmaf(v, g0v.y, acc[1]);
            acc[2]  = fmaf(v, g0v.z, acc[2]);
            acc[3]  = fmaf(v, g0v.w, acc[3]);
            acc[4]  = fmaf(v, g1v.x, acc[4]);
            acc[5]  = fmaf(v, g1v.y, acc[5]);
            acc[6]  = fmaf(v, g1v.z, acc[6]);
            acc[7]  = fmaf(v, g1v.w, acc[7]);
            acc[8]  = fmaf(v, g2v.x, acc[8]);
            acc[9]  = fmaf(v, g2v.y, acc[9]);
            acc[10] = fmaf(v, g2v.z, acc[10]);
            acc[11] = fmaf(v, g2v.w, acc[11]);
            acc[12] = fmaf(v, g3v.x, acc[12]);
            acc[13] = fmaf(v, g3v.y, acc[13]);
            acc[14] = fmaf(v, g3v.z, acc[14]);
            acc[15] = fmaf(v, g3v.w, acc[15]);
        }
    }

    // top-2 (strict > matches jax.lax.top_k first-index tie behavior)
    float v0 = -1e30f, v1 = -1e30f;
    int i0 = 0, i1 = 0;
#pragma unroll
    for (int e = 0; e < NE; ++e) {
        float l = acc[e] + Gb[e];
        if (l > v0)      { v1 = v0; i1 = i0; v0 = l; i0 = e; }
        else if (l > v1) { v1 = l;  i1 = e; }
    }
    float e1 = __expf(v1 - v0);
    float s  = 1.f + e1;
    float ga = 1.f / s;
    float gb2 = e1 / s;

    const int tok = tok0 + tid;
    int p0 = atomicAdd(&g_cnt[i0], 1);
    g_rtok[i0 * NTOK + p0]  = tok;
    g_rgate[i0 * NTOK + p0] = ga;
    int p1 = atomicAdd(&g_cnt[i1], 1);
    g_rtok[i1 * NTOK + p1]  = tok;
    g_rgate[i1 * NTOK + p1] = gb2;
}

// ---------------------------------------------------------------------------
// K3: per-expert fused 3-layer MLP over 32-token tiles + gated scatter-add
// grid = (256 tiles, 16 experts); blocks past the expert's count exit early.
// ---------------------------------------------------------------------------
__global__ __launch_bounds__(256) void expert_kernel(
    const float* __restrict__ x,
    const float* __restrict__ w1, const float* __restrict__ b1,
    const float* __restrict__ w2, const float* __restrict__ b2,
    const float* __restrict__ w3, const float* __restrict__ b3,
    float* __restrict__ out)
{
    const int e = blockIdx.y;
    const int cnt = g_cnt[e];
    const int base = blockIdx.x * 32;
    if (base >= cnt) return;
    const int m = min(32, cnt - base);

    extern __shared__ float sm[];
    float* Xs = sm;                 // [32][256]  32 KB
    float* H1 = Xs + 32 * DIN;      // [32][512]  64 KB
    float* H2 = H1 + 32 * NH;       // [32][512]  64 KB
    __shared__ int   toks[32];
    __shared__ float gts[32];

    const int tid = threadIdx.x;
    if (tid < 32) {
        if (tid < m) {
            toks[tid] = g_rtok[e * NTOK + base + tid];
            gts[tid]  = g_rgate[e * NTOK + base + tid];
        } else {
            toks[tid] = 0; gts[tid] = 0.f;
        }
    }
    __syncthreads();

    for (int idx = tid; idx < 32 * DIN; idx += 256) {
        int r = idx >> 8, i = idx & 255;
        Xs[idx] = (r < m) ? x[(long)toks[r] * DIN + i] : 0.f;
    }
    __syncthreads();

    // h1 = relu(x @ W1[e] + b1[e])   W1: [DIN, E, H], row stride E*H
    gemm32_512(Xs, DIN, w1 + e * NH, (long)NE * NH, b1 + e * NH, H1, NH, true, tid);
    __syncthreads();

    // h2 = relu(h1 @ W2[e] + b2[e])  W2: [H, E, H]
    gemm32_512(H1, NH, w2 + e * NH, (long)NE * NH, b2 + e * NH, H2, NH, true, tid);
    __syncthreads();

    // y = h2 @ W3[e] + b3[e]; out[tok] += gate * y   W3: [H, E, DOUT]
    {
        float acc[32];
#pragma unroll
        for (int r = 0; r < 32; ++r) acc[r] = 0.f;
        const int c = tid;  // 256 threads, 256 output cols
        for (int i = 0; i < NH; i += 4) {
            const float* wp = w3 + (long)i * (NE * DOUT) + e * DOUT;
            float a0 = wp[c]; wp += NE * DOUT;
            float a1 = wp[c]; wp += NE * DOUT;
            float a2 = wp[c]; wp += NE * DOUT;
            float a3 = wp[c];
#pragma unroll
            for (int r = 0; r < 32; ++r) {
                float4 xv = *(const float4*)(H2 + r * NH + i);
                acc[r] = fmaf(xv.x, a0, acc[r]);
                acc[r] = fmaf(xv.y, a1, acc[r]);
                acc[r] = fmaf(xv.z, a2, acc[r]);
                acc[r] = fmaf(xv.w, a3, acc[r]);
            }
        }
        float bb = b3[e * DOUT + c];
        for (int r = 0; r < m; ++r)
            atomicAdd(&out[(long)toks[r] * DOUT + c], gts[r] * (acc[r] + bb));
    }
}

// ---------------------------------------------------------------------------
extern "C" void kernel_launch(void* const* d_in, const int* in_sizes, int n_in,
                              void* d_out, int out_size)
{
    const float* x   = (const float*)d_in[0];
    const float* gw  = (const float*)d_in[1];
    const float* gb  = (const float*)d_in[2];
    const float* gow = (const float*)d_in[3];
    const float* gob = (const float*)d_in[4];
    const float* w1  = (const float*)d_in[5];
    const float* b1  = (const float*)d_in[6];
    const float* w2  = (const float*)d_in[7];
    const float* b2  = (const float*)d_in[8];
    const float* w3  = (const float*)d_in[9];
    const float* b3  = (const float*)d_in[10];
    float* out = (float*)d_out;

    const size_t sm2 = (size_t)(NH * NE + 16 + 128 * 65) * sizeof(float);   // ~66 KB
    const size_t sm3 = (size_t)(32 * DIN + 2 * 32 * NH) * sizeof(float);    // 160 KB
    cudaFuncSetAttribute(gate_route_kernel,
                         cudaFuncAttributeMaxDynamicSharedMemorySize, (int)sm2);
    cudaFuncSetAttribute(expert_kernel,
                         cudaFuncAttributeMaxDynamicSharedMemorySize, (int)sm3);

    cudaMemsetAsync(out, 0, (size_t)NTOK * DOUT * sizeof(float));
    zero_cnt_kernel<<<1, 32>>>();
    gate_h_kernel<<<NTOK / 32, 256>>>(x, gw, gb);
    gate_route_kernel<<<NTOK / 128, 128, sm2>>>(gow, gob);
    expert_kernel<<<dim3(NTOK / 32, NE), 256, sm3>>>(x, w1, b1, w2, b2, w3, b3, out);
}